// round 16
// baseline (speedup 1.0000x reference)
#include <cuda_runtime.h>
#include <cuda_bf16.h>
#include <cuda_fp16.h>
#include <cstdint>
#include <math.h>
#include <math_constants.h>

#define BB 4
#define TT 2048
#define EE 1024
#define DD 128
#define M_TOT (BB*TT)
#define SCALE 0.08838834764831845f

// fp16 operands (written by proj, read by attention). 2 MB each.
__device__ __half g_Q16[M_TOT*DD];
__device__ __half g_K16[M_TOT*DD];
__device__ __half g_V16[M_TOT*DD];
__device__ float2 g_rope[TT*(DD/2)];   // cos/sin table [t][pair]

// ---------------------------------------------------------------------------
// Warp-MMA helpers (sm_80+ baseline PTX — legal on plain sm_100 target)
// ---------------------------------------------------------------------------
__device__ __forceinline__ uint32_t smem_u32(const void* p) {
    uint32_t a;
    asm("{ .reg .u64 t; cvta.to.shared.u64 t, %1; cvt.u32.u64 %0, t; }" : "=r"(a) : "l"(p));
    return a;
}
__device__ __forceinline__ void ldmx4(uint32_t* r, uint32_t addr) {
    asm volatile("ldmatrix.sync.aligned.m8n8.x4.shared.b16 {%0,%1,%2,%3}, [%4];"
        : "=r"(r[0]), "=r"(r[1]), "=r"(r[2]), "=r"(r[3]) : "r"(addr));
}
__device__ __forceinline__ void ldmx4t(uint32_t* r, uint32_t addr) {
    asm volatile("ldmatrix.sync.aligned.m8n8.x4.trans.shared.b16 {%0,%1,%2,%3}, [%4];"
        : "=r"(r[0]), "=r"(r[1]), "=r"(r[2]), "=r"(r[3]) : "r"(addr));
}
__device__ __forceinline__ void mma_bf16(float* c, const uint32_t* a, const uint32_t* b) {
    asm volatile("mma.sync.aligned.m16n8k16.row.col.f32.bf16.bf16.f32 "
        "{%0,%1,%2,%3}, {%4,%5,%6,%7}, {%8,%9}, {%0,%1,%2,%3};"
        : "+f"(c[0]), "+f"(c[1]), "+f"(c[2]), "+f"(c[3])
        : "r"(a[0]), "r"(a[1]), "r"(a[2]), "r"(a[3]), "r"(b[0]), "r"(b[1]));
}
__device__ __forceinline__ void mma_f16(float* c, const uint32_t* a, const uint32_t* b) {
    asm volatile("mma.sync.aligned.m16n8k16.row.col.f32.f16.f16.f32 "
        "{%0,%1,%2,%3}, {%4,%5,%6,%7}, {%8,%9}, {%0,%1,%2,%3};"
        : "+f"(c[0]), "+f"(c[1]), "+f"(c[2]), "+f"(c[3])
        : "r"(a[0]), "r"(a[1]), "r"(a[2]), "r"(a[3]), "r"(b[0]), "r"(b[1]));
}
#define CP16(dst, src) \
    asm volatile("cp.async.cg.shared.global [%0], [%1], 16;" :: "r"(dst), "l"(src))
#define CPCOMMIT() asm volatile("cp.async.commit_group;" ::: "memory")
#define CPWAIT1()  asm volatile("cp.async.wait_group 1;" ::: "memory")
#define CPWAIT0()  asm volatile("cp.async.wait_group 0;" ::: "memory")

__device__ __forceinline__ void split4(float4 v, uint2& hi, uint2& lo) {
    float f[4] = {v.x, v.y, v.z, v.w};
    unsigned short h[4], l[4];
#pragma unroll
    for (int i = 0; i < 4; i++) {
        __nv_bfloat16 bh = __float2bfloat16(f[i]);
        h[i] = __bfloat16_as_ushort(bh);
        float r = f[i] - __bfloat162float(bh);
        l[i] = __bfloat16_as_ushort(__float2bfloat16(r));
    }
    hi.x = (uint32_t)h[0] | ((uint32_t)h[1] << 16);
    hi.y = (uint32_t)h[2] | ((uint32_t)h[3] << 16);
    lo.x = (uint32_t)l[0] | ((uint32_t)l[1] << 16);
    lo.y = (uint32_t)l[2] | ((uint32_t)l[3] << 16);
}
__device__ __forceinline__ uint32_t pack_h2(float a, float b) {
    __half2 h = __floats2half2_rn(a, b);
    return *reinterpret_cast<uint32_t*>(&h);
}

// swizzled byte offset inside a 128-col 16-bit tile (256 B rows)
__device__ __forceinline__ uint32_t swz(uint32_t row, uint32_t col) {
    return row*256u + ((((col>>3) ^ (row&7)))<<4) + (col&7)*2u;
}

// ---------------------------------------------------------------------------
// RoPE table
// ---------------------------------------------------------------------------
__global__ __launch_bounds__(256)
void rope_table_kernel()
{
    int idx = blockIdx.x * blockDim.x + threadIdx.x;
    if (idx >= TT * (DD/2)) return;
    int i = idx & 63;
    int t = idx >> 6;
    float freq = exp2f(-0.20762050593046777f * (float)i);
    float ang = (float)t * freq;
    float s, c;
    sincosf(ang, &s, &c);
    g_rope[idx] = make_float2(c, s);
}

// ===========================================================================
// Projection via mma.sync bf16 3-term split; RoPE fused; writes fp16.
// BM=64 (grid 384 for wave packing). 8 warps: 2(wm) x 4(wn). BK=32 double-buf.
// ===========================================================================
#define STR 40
#define TILE_A (64*STR)
#define TILE_B (128*STR)
#define STAGE_ELEMS (2*TILE_A + 2*TILE_B)
#define OFF_AL (TILE_A*2)
#define OFF_BH (2*TILE_A*2)
#define OFF_BL ((2*TILE_A + TILE_B)*2)
#define PROJ_SMEM_BYTES (2*STAGE_ELEMS*2)

extern __shared__ char proj_sm[];

__global__ __launch_bounds__(256)
void proj_mma_kernel(const float* __restrict__ X,
                     const float* __restrict__ wQ,
                     const float* __restrict__ wK,
                     const float* __restrict__ wV)
{
    const int tid  = threadIdx.x;
    const int wid  = tid >> 5;
    const int lane = tid & 31;
    const int m0   = blockIdx.x * 64;
    const int wsel = blockIdx.y;
    const float* W = (wsel == 0) ? wQ : (wsel == 1) ? wK : wV;
    __half* o16    = (wsel == 0) ? g_Q16 : (wsel == 1) ? g_K16 : g_V16;

    const int wm = wid >> 2;
    const int wn = wid & 3;

    const uint32_t sbase = smem_u32(proj_sm);
    __nv_bfloat16* sm16 = reinterpret_cast<__nv_bfloat16*>(proj_sm);

    const int arow = tid >> 2;
    const int acb  = (tid & 3) * 8;
    const int brow = tid >> 1;
    const int bcb  = (tid & 1) * 16;

    float4 px[2][2], pw[2][4];
#pragma unroll
    for (int j = 0; j < 2; j++)
        px[0][j] = *reinterpret_cast<const float4*>(&X[(size_t)(m0 + arow) * EE + acb + 4*j]);
#pragma unroll
    for (int j = 0; j < 4; j++)
        pw[0][j] = *reinterpret_cast<const float4*>(&W[(size_t)brow * EE + bcb + 4*j]);

    float acc[2][4][4];
#pragma unroll
    for (int mf = 0; mf < 2; mf++)
#pragma unroll
        for (int nf = 0; nf < 4; nf++)
#pragma unroll
            for (int q = 0; q < 4; q++) acc[mf][nf][q] = 0.f;

    for (int c = 0; c < 32; c++) {
        const int buf = c & 1;
        __nv_bfloat16* Ah = sm16 + buf * STAGE_ELEMS;
        __nv_bfloat16* Al = Ah + TILE_A;
        __nv_bfloat16* Bh = Ah + 2*TILE_A;
        __nv_bfloat16* Bl = Bh + TILE_B;

#pragma unroll
        for (int j = 0; j < 2; j++) {
            const int col = acb + 4*j;
            uint2 hi, lo;
            split4(px[buf][j], hi, lo);
            *reinterpret_cast<uint2*>(&Ah[arow*STR + col]) = hi;
            *reinterpret_cast<uint2*>(&Al[arow*STR + col]) = lo;
        }
#pragma unroll
        for (int j = 0; j < 4; j++) {
            const int col = bcb + 4*j;
            uint2 hi, lo;
            split4(pw[buf][j], hi, lo);
            *reinterpret_cast<uint2*>(&Bh[brow*STR + col]) = hi;
            *reinterpret_cast<uint2*>(&Bl[brow*STR + col]) = lo;
        }

        if (c + 1 < 32) {
            const int k0 = (c + 1) * 32;
            const int nb = (c + 1) & 1;
#pragma unroll
            for (int j = 0; j < 2; j++)
                px[nb][j] = *reinterpret_cast<const float4*>(&X[(size_t)(m0 + arow) * EE + k0 + acb + 4*j]);
#pragma unroll
            for (int j = 0; j < 4; j++)
                pw[nb][j] = *reinterpret_cast<const float4*>(&W[(size_t)brow * EE + k0 + bcb + 4*j]);
        }

        __syncthreads();

        const uint32_t stage = sbase + buf * (STAGE_ELEMS * 2);
#pragma unroll
        for (int kb = 0; kb < 32; kb += 16) {
            uint32_t ah[2][4], al[2][4];
#pragma unroll
            for (int mf = 0; mf < 2; mf++) {
                const int row = 32*wm + 16*mf + (lane & 15);
                const int col = kb + 8*(lane >> 4);
                const uint32_t addrA = stage + (uint32_t)(row*STR + col) * 2;
                ldmx4(ah[mf], addrA);
                ldmx4(al[mf], addrA + OFF_AL);
            }
            uint32_t bh[4][2], bl[4][2];
#pragma unroll
            for (int nb4 = 0; nb4 < 2; nb4++) {
                const int n   = 32*wn + 16*nb4 + (lane & 7) + ((lane & 16) >> 1);
                const int col = kb + (lane & 8);
                const uint32_t addrB = stage + OFF_BH + (uint32_t)(n*STR + col) * 2;
                uint32_t r[4];
                ldmx4(r, addrB);
                bh[2*nb4][0] = r[0]; bh[2*nb4][1] = r[1];
                bh[2*nb4+1][0] = r[2]; bh[2*nb4+1][1] = r[3];
                ldmx4(r, addrB + (OFF_BL - OFF_BH));
                bl[2*nb4][0] = r[0]; bl[2*nb4][1] = r[1];
                bl[2*nb4+1][0] = r[2]; bl[2*nb4+1][1] = r[3];
            }
#pragma unroll
            for (int mf = 0; mf < 2; mf++)
#pragma unroll
                for (int nf = 0; nf < 4; nf++) {
                    mma_bf16(acc[mf][nf], ah[mf], bh[nf]);
                    mma_bf16(acc[mf][nf], ah[mf], bl[nf]);
                    mma_bf16(acc[mf][nf], al[mf], bh[nf]);
                }
        }
        __syncthreads();
    }

    const bool do_rope = (wsel < 2);
    const bool do_scale = (wsel == 0);
#pragma unroll
    for (int mf = 0; mf < 2; mf++) {
#pragma unroll
        for (int half = 0; half < 2; half++) {
            const int row = m0 + 32*wm + 16*mf + (lane >> 2) + 8*half;
            const int t = row & (TT - 1);
#pragma unroll
            for (int nf = 0; nf < 4; nf++) {
                const int col = 32*wn + 8*nf + 2*(lane & 3);
                float x0 = acc[mf][nf][2*half];
                float x1 = acc[mf][nf][2*half + 1];
                if (do_rope) {
                    float2 cs = g_rope[t * 64 + (col >> 1)];
                    float r0 = x0 * cs.x - x1 * cs.y;
                    float r1 = x0 * cs.y + x1 * cs.x;
                    x0 = r0; x1 = r1;
                }
                if (do_scale) { x0 *= SCALE; x1 *= SCALE; }
                *reinterpret_cast<uint32_t*>(&o16[(size_t)row * DD + col]) = pack_h2(x0, x1);
            }
        }
    }
}

// ===========================================================================
// Tensor-core flash attention, BM=64, single-term fp16, P-in-registers.
// 128 CTAs (one 64-row q-tile each). 8 warps = 4(wm: 16 rows) x 2(wk: 32 keys).
// Per tile/warp: S 32 mma, PV 32 mma; O partials reduced across wk per q-tile.
// ===========================================================================
#define A_Q  0                 // Q fp16 staging (16 KB, 64 rows)
#define A_K  16384             // K double buf (2 x 16 KB)
#define A_V  49152             // V double buf (2 x 16 KB) -> ends 81920
#define A_PART 0               // O-partial scratch (reuse all; 8 x 8448 = 67584)
#define A_SUM 81920            // 64 rows x 2 x 4 B = 512
#define ATTN_SMEM 82432
#define PART_ROW 528           // O-partial row stride (132 floats)
#define PART_REG 8448          // 16*528 per warp

extern __shared__ char attn_smc[];

__device__ __forceinline__ void issue_kv(uint32_t sb, int buf, int tid,
                                         const __half* Kp, const __half* Vp,
                                         int kbase)
{
    const int row = tid >> 2;            // 0..63
    const int ch0 = (tid & 3) * 4;
    const size_t gb = ((size_t)(kbase + row)) * DD;
    const uint32_t kb = sb + A_K + buf * 16384;
    const uint32_t vb = sb + A_V + buf * 16384;
#pragma unroll
    for (int j = 0; j < 4; j++) {
        const int ch = ch0 + j;
        const uint32_t d = swz(row, ch * 8);
        CP16(kb + d, Kp + gb + ch*8);
        CP16(vb + d, Vp + gb + ch*8);
    }
}

__global__ __launch_bounds__(256)
void attn_mma_kernel(float* __restrict__ out)
{
    const uint32_t sb = smem_u32(attn_smc);
    const int tid  = threadIdx.x;
    const int wid  = tid >> 5;
    const int lane = tid & 31;
    const int wm   = wid >> 1;           // 0..3: 16-row group
    const int wk   = wid & 1;            // 0..1: 32-key slice
    const int b    = blockIdx.x & 3;
    const int qt   = blockIdx.x >> 2;    // 0..31

    const __half* Qp = g_Q16 + (size_t)b*TT*DD;
    const __half* Kp = g_K16 + (size_t)b*TT*DD;
    const __half* Vp = g_V16 + (size_t)b*TT*DD;

    float* sums = reinterpret_cast<float*>(attn_smc + A_SUM);

    const int q0 = qt * 64;
    const int ntiles = q0 / 64 + 1;

    // stage Q tile (64 rows) into swizzled smem
    {
        const int row = tid >> 2;            // 0..63
        const int ch0 = (tid & 3) * 4;
#pragma unroll
        for (int j = 0; j < 4; j++) {
            const int ch = ch0 + j;
            const size_t gq = ((size_t)(q0 + row)) * DD + ch*8;
            *reinterpret_cast<uint4*>(attn_smc + A_Q + swz(row, ch*8)) =
                *reinterpret_cast<const uint4*>(Qp + gq);
        }
    }
    issue_kv(sb, 0, tid, Kp, Vp, 0);
    CPCOMMIT();
    if (ntiles > 1) issue_kv(sb, 1, tid, Kp, Vp, 64);
    CPCOMMIT();
    __syncthreads();

    // hoist Q fragments into registers (whole K-dim)
    uint32_t qf[8][4];
    {
        const int aRow = 16*wm + (lane & 15);
        const int aCol = 8 * (lane >> 4);
#pragma unroll
        for (int kc = 0; kc < 8; kc++)
            ldmx4(qf[kc], sb + A_Q + swz(aRow, kc*16 + aCol));
    }

    float lsum[2] = {0.f, 0.f};
    float O[16][4];
#pragma unroll
    for (int nf = 0; nf < 16; nf++)
#pragma unroll
        for (int q = 0; q < 4; q++) O[nf][q] = 0.f;

    for (int t = 0; t < ntiles; t++) {
        const int buf = t & 1;
        const int kbase = t * 64;
        const uint32_t kBuf = sb + A_K + buf*16384;
        const uint32_t vBuf = sb + A_V + buf*16384;

        CPWAIT1();
        __syncthreads();

        // ---- S = Q @ K^T over warp's 32 keys ----
        float S[4][4];
#pragma unroll
        for (int nf = 0; nf < 4; nf++)
#pragma unroll
            for (int q = 0; q < 4; q++) S[nf][q] = 0.f;

        const int bR = (lane & 7) + ((lane & 16) >> 1);
        const int bCol = lane & 8;
#pragma unroll
        for (int kc = 0; kc < 8; kc++) {
            uint32_t rb[4];
            ldmx4(rb, kBuf + swz(32*wk + bR, kc*16 + bCol));
            uint32_t k0f[2] = {rb[0], rb[1]};
            uint32_t k1f[2] = {rb[2], rb[3]};
            mma_f16(S[0], qf[kc], k0f);
            mma_f16(S[1], qf[kc], k1f);
            ldmx4(rb, kBuf + swz(32*wk + 16 + bR, kc*16 + bCol));
            uint32_t k2f[2] = {rb[0], rb[1]};
            uint32_t k3f[2] = {rb[2], rb[3]};
            mma_f16(S[2], qf[kc], k2f);
            mma_f16(S[3], qf[kc], k3f);
        }

        // ---- p = exp(s) (masked -> 0); pack to PV A-frags (2 k16 chunks) ----
        const bool lastt = (t == ntiles - 1);
        uint32_t pf[2][4];
#pragma unroll
        for (int nf = 0; nf < 4; nf++)
#pragma unroll
            for (int h = 0; h < 2; h++) {
                const int gcol0 = kbase + 32*wk + 8*nf + 2*(lane & 3);
                const int grow  = q0 + 16*wm + (lane >> 2) + 8*h;
                float p0 = (lastt && gcol0     > grow) ? 0.f : __expf(S[nf][2*h]);
                float p1 = (lastt && gcol0 + 1 > grow) ? 0.f : __expf(S[nf][2*h+1]);
                lsum[h] += p0 + p1;
                pf[nf >> 1][(nf & 1)*2 + h] = pack_h2(p0, p1);
            }

        // ---- O += P @ V  (warp's 32 keys x all 128 D, 2 k16 chunks) ----
        const int dc8 = 8 * (lane >> 4);
#pragma unroll
        for (int c = 0; c < 2; c++) {
            const int key = 32*wk + 16*c + (lane & 15);
#pragma unroll
            for (int j = 0; j < 8; j++) {
                uint32_t r[4];
                ldmx4t(r, vBuf + swz(key, 16*j + dc8));
                uint32_t vb0[2] = {r[0], r[1]};
                uint32_t vb1[2] = {r[2], r[3]};
                mma_f16(O[2*j],   pf[c], vb0);
                mma_f16(O[2*j+1], pf[c], vb1);
            }
        }

        __syncthreads();
        if (t + 2 < ntiles) issue_kv(sb, buf, tid, Kp, Vp, (t + 2) * 64);
        CPCOMMIT();
    }

    // ---- row-sum partials (2 wk groups) ----
#pragma unroll
    for (int h = 0; h < 2; h++) {
        float v = lsum[h];
        v += __shfl_xor_sync(0xffffffff, v, 1);
        v += __shfl_xor_sync(0xffffffff, v, 2);
        if ((lane & 3) == 0)
            sums[(16*wm + (lane >> 2) + 8*h)*2 + wk] = v;
    }

    // ---- drain cp.async; reuse smem for O-partial reduction ----
    CPWAIT0();
    __syncthreads();
    {
        char* preg = attn_smc + A_PART + wid * PART_REG;
        const int r0 = lane >> 2;
#pragma unroll
        for (int nf = 0; nf < 16; nf++) {
            const int col = 8*nf + 2*(lane & 3);
            *reinterpret_cast<float2*>(preg + r0*PART_ROW + col*4) =
                make_float2(O[nf][0], O[nf][1]);
            *reinterpret_cast<float2*>(preg + (r0+8)*PART_ROW + col*4) =
                make_float2(O[nf][2], O[nf][3]);
        }
    }
    __syncthreads();
    {
        const int rr  = tid >> 2;            // 0..63 (q row)
        const int cc  = (tid & 3) * 32;      // col base (floats)
        const int wmh = rr >> 4;
        const int lr  = rr & 15;
        float2 sp = *reinterpret_cast<float2*>(&sums[rr*2]);
        const float inv = 1.f / (sp.x + sp.y);
        const size_t ob = ((size_t)(b*TT + q0 + rr)) * DD + cc;
#pragma unroll
        for (int s4 = 0; s4 < 8; s4++) {
            float4 a = make_float4(0.f, 0.f, 0.f, 0.f);
#pragma unroll
            for (int k = 0; k < 2; k++) {
                const float4 v = *reinterpret_cast<const float4*>(
                    attn_smc + A_PART + (wmh*2 + k)*PART_REG + lr*PART_ROW + (cc + s4*4)*4);
                a.x += v.x; a.y += v.y; a.z += v.z; a.w += v.w;
            }
            *reinterpret_cast<float4*>(&out[ob + s4*4]) =
                make_float4(a.x*inv, a.y*inv, a.z*inv, a.w*inv);
        }
    }
}

// ---------------------------------------------------------------------------
extern "C" void kernel_launch(void* const* d_in, const int* in_sizes, int n_in,
                              void* d_out, int out_size)
{
    const float* X  = (const float*)d_in[0];
    const float* wQ = (const float*)d_in[1];
    const float* wK = (const float*)d_in[2];
    const float* wV = (const float*)d_in[3];
    float* out = (float*)d_out;

    cudaFuncSetAttribute(proj_mma_kernel, cudaFuncAttributeMaxDynamicSharedMemorySize,
                         PROJ_SMEM_BYTES);
    cudaFuncSetAttribute(attn_mma_kernel, cudaFuncAttributeMaxDynamicSharedMemorySize,
                         ATTN_SMEM);

    rope_table_kernel<<<(TT * (DD/2) + 255) / 256, 256>>>();
    proj_mma_kernel<<<dim3(M_TOT / 64, 3), 256, PROJ_SMEM_BYTES>>>(X, wQ, wK, wV);
    attn_mma_kernel<<<BB * 32, 256, ATTN_SMEM>>>(out);
}

// round 17
// speedup vs baseline: 1.2055x; 1.2055x over previous
#include <cuda_runtime.h>
#include <cuda_bf16.h>
#include <cuda_fp16.h>
#include <cstdint>
#include <math.h>
#include <math_constants.h>

#define BB 4
#define TT 2048
#define EE 1024
#define DD 128
#define M_TOT (BB*TT)
#define SCALE 0.08838834764831845f

// fp16 operands (written by proj, read by attention). 2 MB each.
__device__ __half g_Q16[M_TOT*DD];
__device__ __half g_K16[M_TOT*DD];
__device__ __half g_V16[M_TOT*DD];
__device__ float2 g_rope[TT*(DD/2)];   // cos/sin table [t][pair]

// ---------------------------------------------------------------------------
// Warp-MMA helpers (sm_80+ baseline PTX — legal on plain sm_100 target)
// ---------------------------------------------------------------------------
__device__ __forceinline__ uint32_t smem_u32(const void* p) {
    uint32_t a;
    asm("{ .reg .u64 t; cvta.to.shared.u64 t, %1; cvt.u32.u64 %0, t; }" : "=r"(a) : "l"(p));
    return a;
}
__device__ __forceinline__ void ldmx4(uint32_t* r, uint32_t addr) {
    asm volatile("ldmatrix.sync.aligned.m8n8.x4.shared.b16 {%0,%1,%2,%3}, [%4];"
        : "=r"(r[0]), "=r"(r[1]), "=r"(r[2]), "=r"(r[3]) : "r"(addr));
}
__device__ __forceinline__ void ldmx4t(uint32_t* r, uint32_t addr) {
    asm volatile("ldmatrix.sync.aligned.m8n8.x4.trans.shared.b16 {%0,%1,%2,%3}, [%4];"
        : "=r"(r[0]), "=r"(r[1]), "=r"(r[2]), "=r"(r[3]) : "r"(addr));
}
__device__ __forceinline__ void mma_f16(float* c, const uint32_t* a, const uint32_t* b) {
    asm volatile("mma.sync.aligned.m16n8k16.row.col.f32.f16.f16.f32 "
        "{%0,%1,%2,%3}, {%4,%5,%6,%7}, {%8,%9}, {%0,%1,%2,%3};"
        : "+f"(c[0]), "+f"(c[1]), "+f"(c[2]), "+f"(c[3])
        : "r"(a[0]), "r"(a[1]), "r"(a[2]), "r"(a[3]), "r"(b[0]), "r"(b[1]));
}
#define CP16(dst, src) \
    asm volatile("cp.async.cg.shared.global [%0], [%1], 16;" :: "r"(dst), "l"(src))
#define CPCOMMIT() asm volatile("cp.async.commit_group;" ::: "memory")
#define CPWAIT1()  asm volatile("cp.async.wait_group 1;" ::: "memory")
#define CPWAIT0()  asm volatile("cp.async.wait_group 0;" ::: "memory")

__device__ __forceinline__ uint32_t pack_h2(float a, float b) {
    __half2 h = __floats2half2_rn(a, b);
    return *reinterpret_cast<uint32_t*>(&h);
}
__device__ __forceinline__ uint2 pack4_h(float4 v) {
    uint2 r;
    __half2 a = __floats2half2_rn(v.x, v.y);
    __half2 b = __floats2half2_rn(v.z, v.w);
    r.x = *reinterpret_cast<uint32_t*>(&a);
    r.y = *reinterpret_cast<uint32_t*>(&b);
    return r;
}
__device__ __forceinline__ void split4_h(float4 v, uint2& hi, uint2& lo) {
    float f[4] = {v.x, v.y, v.z, v.w};
    unsigned short h[4], l[4];
#pragma unroll
    for (int i = 0; i < 4; i++) {
        __half hh = __float2half_rn(f[i]);
        h[i] = __half_as_ushort(hh);
        float r = f[i] - __half2float(hh);
        l[i] = __half_as_ushort(__float2half_rn(r));
    }
    hi.x = (uint32_t)h[0] | ((uint32_t)h[1] << 16);
    hi.y = (uint32_t)h[2] | ((uint32_t)h[3] << 16);
    lo.x = (uint32_t)l[0] | ((uint32_t)l[1] << 16);
    lo.y = (uint32_t)l[2] | ((uint32_t)l[3] << 16);
}

// swizzled byte offset inside a 128-col 16-bit tile (256 B rows)
__device__ __forceinline__ uint32_t swz(uint32_t row, uint32_t col) {
    return row*256u + ((((col>>3) ^ (row&7)))<<4) + (col&7)*2u;
}

// ---------------------------------------------------------------------------
// RoPE table
// ---------------------------------------------------------------------------
__global__ __launch_bounds__(256)
void rope_table_kernel()
{
    int idx = blockIdx.x * blockDim.x + threadIdx.x;
    if (idx >= TT * (DD/2)) return;
    int i = idx & 63;
    int t = idx >> 6;
    float freq = exp2f(-0.20762050593046777f * (float)i);
    float ang = (float)t * freq;
    float s, c;
    sincosf(ang, &s, &c);
    g_rope[idx] = make_float2(c, s);
}

// ===========================================================================
// Projection via mma.sync fp16 2-term split-W: out = x16·Wh^T + x16·Wl^T.
// BM=64, grid (128, 3). 8 warps: 2(wm) x 4(wn). BK=32 double-buffered.
// RoPE fused; Q pre-scaled by 1/sqrt(d); writes fp16.
// ===========================================================================
#define STR 40
#define TILE_A (64*STR)                 // 2560 elems (A, single fp16)
#define TILE_B (128*STR)                // 5120 elems
#define STAGE_ELEMS (TILE_A + 2*TILE_B) // 12800
#define OFF_BH (TILE_A*2)
#define OFF_BL ((TILE_A + TILE_B)*2)
#define PROJ_SMEM_BYTES (2*STAGE_ELEMS*2)   // 51200 B

extern __shared__ char proj_sm[];

__global__ __launch_bounds__(256)
void proj_mma_kernel(const float* __restrict__ X,
                     const float* __restrict__ wQ,
                     const float* __restrict__ wK,
                     const float* __restrict__ wV)
{
    const int tid  = threadIdx.x;
    const int wid  = tid >> 5;
    const int lane = tid & 31;
    const int m0   = blockIdx.x * 64;
    const int wsel = blockIdx.y;
    const float* W = (wsel == 0) ? wQ : (wsel == 1) ? wK : wV;
    __half* o16    = (wsel == 0) ? g_Q16 : (wsel == 1) ? g_K16 : g_V16;

    const int wm = wid >> 2;   // 0..1 -> M offset 32*wm
    const int wn = wid & 3;    // 0..3 -> N offset 32*wn

    const uint32_t sbase = smem_u32(proj_sm);
    __half* sm16 = reinterpret_cast<__half*>(proj_sm);

    const int arow = tid >> 2;          // 0..63
    const int acb  = (tid & 3) * 8;
    const int brow = tid >> 1;          // 0..127
    const int bcb  = (tid & 1) * 16;

    float4 px[2][2], pw[2][4];
#pragma unroll
    for (int j = 0; j < 2; j++)
        px[0][j] = *reinterpret_cast<const float4*>(&X[(size_t)(m0 + arow) * EE + acb + 4*j]);
#pragma unroll
    for (int j = 0; j < 4; j++)
        pw[0][j] = *reinterpret_cast<const float4*>(&W[(size_t)brow * EE + bcb + 4*j]);

    float acc[2][4][4];
#pragma unroll
    for (int mf = 0; mf < 2; mf++)
#pragma unroll
        for (int nf = 0; nf < 4; nf++)
#pragma unroll
            for (int q = 0; q < 4; q++) acc[mf][nf][q] = 0.f;

    for (int c = 0; c < 32; c++) {
        const int buf = c & 1;
        __half* Ah = sm16 + buf * STAGE_ELEMS;
        __half* Bh = Ah + TILE_A;
        __half* Bl = Bh + TILE_B;

#pragma unroll
        for (int j = 0; j < 2; j++) {
            const int col = acb + 4*j;
            *reinterpret_cast<uint2*>(&Ah[arow*STR + col]) = pack4_h(px[buf][j]);
        }
#pragma unroll
        for (int j = 0; j < 4; j++) {
            const int col = bcb + 4*j;
            uint2 hi, lo;
            split4_h(pw[buf][j], hi, lo);
            *reinterpret_cast<uint2*>(&Bh[brow*STR + col]) = hi;
            *reinterpret_cast<uint2*>(&Bl[brow*STR + col]) = lo;
        }

        if (c + 1 < 32) {
            const int k0 = (c + 1) * 32;
            const int nb = (c + 1) & 1;
#pragma unroll
            for (int j = 0; j < 2; j++)
                px[nb][j] = *reinterpret_cast<const float4*>(&X[(size_t)(m0 + arow) * EE + k0 + acb + 4*j]);
#pragma unroll
            for (int j = 0; j < 4; j++)
                pw[nb][j] = *reinterpret_cast<const float4*>(&W[(size_t)brow * EE + k0 + bcb + 4*j]);
        }

        __syncthreads();

        const uint32_t stage = sbase + buf * (STAGE_ELEMS * 2);
#pragma unroll
        for (int kb = 0; kb < 32; kb += 16) {
            uint32_t ah[2][4];
#pragma unroll
            for (int mf = 0; mf < 2; mf++) {
                const int row = 32*wm + 16*mf + (lane & 15);
                const int col = kb + 8*(lane >> 4);
                ldmx4(ah[mf], stage + (uint32_t)(row*STR + col) * 2);
            }
            uint32_t bh[4][2], bl[4][2];
#pragma unroll
            for (int nb4 = 0; nb4 < 2; nb4++) {
                const int n   = 32*wn + 16*nb4 + (lane & 7) + ((lane & 16) >> 1);
                const int col = kb + (lane & 8);
                const uint32_t addrB = stage + OFF_BH + (uint32_t)(n*STR + col) * 2;
                uint32_t r[4];
                ldmx4(r, addrB);
                bh[2*nb4][0] = r[0]; bh[2*nb4][1] = r[1];
                bh[2*nb4+1][0] = r[2]; bh[2*nb4+1][1] = r[3];
                ldmx4(r, addrB + (OFF_BL - OFF_BH));
                bl[2*nb4][0] = r[0]; bl[2*nb4][1] = r[1];
                bl[2*nb4+1][0] = r[2]; bl[2*nb4+1][1] = r[3];
            }
#pragma unroll
            for (int mf = 0; mf < 2; mf++)
#pragma unroll
                for (int nf = 0; nf < 4; nf++) {
                    mma_f16(acc[mf][nf], ah[mf], bh[nf]);
                    mma_f16(acc[mf][nf], ah[mf], bl[nf]);
                }
        }
        __syncthreads();
    }

    // epilogue: RoPE (Q/K), Q pre-scale, fp16 store
    const bool do_rope = (wsel < 2);
    const bool do_scale = (wsel == 0);
#pragma unroll
    for (int mf = 0; mf < 2; mf++) {
#pragma unroll
        for (int half = 0; half < 2; half++) {
            const int row = m0 + 32*wm + 16*mf + (lane >> 2) + 8*half;
            const int t = row & (TT - 1);
#pragma unroll
            for (int nf = 0; nf < 4; nf++) {
                const int col = 32*wn + 8*nf + 2*(lane & 3);
                float x0 = acc[mf][nf][2*half];
                float x1 = acc[mf][nf][2*half + 1];
                if (do_rope) {
                    float2 cs = g_rope[t * 64 + (col >> 1)];
                    float r0 = x0 * cs.x - x1 * cs.y;
                    float r1 = x0 * cs.y + x1 * cs.x;
                    x0 = r0; x1 = r1;
                }
                if (do_scale) { x0 *= SCALE; x1 *= SCALE; }
                *reinterpret_cast<uint32_t*>(&o16[(size_t)row * DD + col]) = pack_h2(x0, x1);
            }
        }
    }
}

// ===========================================================================
// Tensor-core flash attention, single-term fp16, P-in-registers (R15 exact).
// 256 CTAs (one 32-row q-tile each), big-first order, batches interleaved.
// ===========================================================================
#define A_Q  0                 // Q fp16 staging (8 KB)
#define A_K  8192              // K double buf (2 x 16 KB)
#define A_V  40960             // V double buf (2 x 16 KB) -> ends 73728
#define A_PART 8192            // O-partial scratch (overlaps K/V; 8 x 8448 = 67584 -> ends 75776)
#define A_SUM 75776            // 512 B
#define ATTN_SMEM 76288
#define PART_ROW 528           // O-partial row stride (132 floats)
#define PART_REG 8448          // 16*528 per warp

extern __shared__ char attn_smc[];

__device__ __forceinline__ void issue_kv(uint32_t sb, int buf, int tid,
                                         const __half* Kp, const __half* Vp,
                                         int kbase)
{
    const int row = tid >> 2;            // 0..63
    const int ch0 = (tid & 3) * 4;
    const size_t gb = ((size_t)(kbase + row)) * DD;
    const uint32_t kb = sb + A_K + buf * 16384;
    const uint32_t vb = sb + A_V + buf * 16384;
#pragma unroll
    for (int j = 0; j < 4; j++) {
        const int ch = ch0 + j;
        const uint32_t d = swz(row, ch * 8);
        CP16(kb + d, Kp + gb + ch*8);
        CP16(vb + d, Vp + gb + ch*8);
    }
}

__global__ __launch_bounds__(256)
void attn_mma_kernel(float* __restrict__ out)
{
    const uint32_t sb = smem_u32(attn_smc);
    const int tid  = threadIdx.x;
    const int wid  = tid >> 5;
    const int lane = tid & 31;
    const int wm   = wid >> 2;           // 0..1: M half (16 rows)
    const int wk   = wid & 3;            // 0..3: 16-key slice
    const int b    = blockIdx.x & 3;     // batches interleaved
    const int qt   = 63 - (blockIdx.x >> 2);   // big-first

    const __half* Qp = g_Q16 + (size_t)b*TT*DD;
    const __half* Kp = g_K16 + (size_t)b*TT*DD;
    const __half* Vp = g_V16 + (size_t)b*TT*DD;

    float* sums = reinterpret_cast<float*>(attn_smc + A_SUM);

    const int q0 = qt * 32;
    const int ntiles = q0 / 64 + 1;

    // stage Q tile into swizzled smem
    {
        const int row = tid >> 3;            // 0..31
        const int cb  = (tid & 7) * 2;
#pragma unroll
        for (int j = 0; j < 2; j++) {
            const int ch = cb + j;
            const size_t gq = ((size_t)(q0 + row)) * DD + ch*8;
            *reinterpret_cast<uint4*>(attn_smc + A_Q + swz(row, ch*8)) =
                *reinterpret_cast<const uint4*>(Qp + gq);
        }
    }
    issue_kv(sb, 0, tid, Kp, Vp, 0);
    CPCOMMIT();
    if (ntiles > 1) issue_kv(sb, 1, tid, Kp, Vp, 64);
    CPCOMMIT();
    __syncthreads();

    // hoist Q fragments into registers (whole K-dim)
    uint32_t qf[8][4];
    {
        const int aRow = 16*wm + (lane & 15);
        const int aCol = 8 * (lane >> 4);
#pragma unroll
        for (int kc = 0; kc < 8; kc++)
            ldmx4(qf[kc], sb + A_Q + swz(aRow, kc*16 + aCol));
    }

    float lsum[2] = {0.f, 0.f};
    float O[16][4];
#pragma unroll
    for (int nf = 0; nf < 16; nf++)
#pragma unroll
        for (int q = 0; q < 4; q++) O[nf][q] = 0.f;

    for (int t = 0; t < ntiles; t++) {
        const int buf = t & 1;
        const int kbase = t * 64;
        const uint32_t kBuf = sb + A_K + buf*16384;
        const uint32_t vBuf = sb + A_V + buf*16384;

        CPWAIT1();
        __syncthreads();

        // ---- S = Q @ K^T (fp16 single-term) ----
        float S[2][4];
#pragma unroll
        for (int nf = 0; nf < 2; nf++)
#pragma unroll
            for (int q = 0; q < 4; q++) S[nf][q] = 0.f;

        const int bRow = 16*wk + (lane & 7) + ((lane & 16) >> 1);
        const int bCol = lane & 8;
#pragma unroll
        for (int kc = 0; kc < 8; kc++) {
            uint32_t rb[4];
            ldmx4(rb, kBuf + swz(bRow, kc*16 + bCol));
            uint32_t kb0[2] = {rb[0], rb[1]};
            uint32_t kb1[2] = {rb[2], rb[3]};
            mma_f16(S[0], qf[kc], kb0);
            mma_f16(S[1], qf[kc], kb1);
        }

        // ---- p = exp(s) (masked -> 0); pack C-frags directly to PV A-frags ----
        const bool lastt = (t == ntiles - 1);
        uint32_t pf[4];
#pragma unroll
        for (int nf = 0; nf < 2; nf++)
#pragma unroll
            for (int h = 0; h < 2; h++) {
                const int gcol0 = kbase + 16*wk + 8*nf + 2*(lane & 3);
                const int grow  = q0 + 16*wm + (lane >> 2) + 8*h;
                float p0 = (lastt && gcol0     > grow) ? 0.f : __expf(S[nf][2*h]);
                float p1 = (lastt && gcol0 + 1 > grow) ? 0.f : __expf(S[nf][2*h+1]);
                lsum[h] += p0 + p1;
                pf[nf*2 + h] = pack_h2(p0, p1);
            }

        // ---- O += P @ V  (warp's 16 keys x all 128 D) ----
        const int key = 16*wk + (lane & 15);
        const int dc8 = 8 * (lane >> 4);
#pragma unroll
        for (int j = 0; j < 8; j++) {
            uint32_t r[4];
            ldmx4t(r, vBuf + swz(key, 16*j + dc8));
            uint32_t vb0[2] = {r[0], r[1]};
            uint32_t vb1[2] = {r[2], r[3]};
            mma_f16(O[2*j],   pf, vb0);
            mma_f16(O[2*j+1], pf, vb1);
        }

        __syncthreads();
        if (t + 2 < ntiles) issue_kv(sb, buf, tid, Kp, Vp, (t + 2) * 64);
        CPCOMMIT();
    }

    // ---- row-sum partials ----
#pragma unroll
    for (int h = 0; h < 2; h++) {
        float v = lsum[h];
        v += __shfl_xor_sync(0xffffffff, v, 1);
        v += __shfl_xor_sync(0xffffffff, v, 2);
        if ((lane & 3) == 0)
            sums[(16*wm + (lane >> 2) + 8*h)*4 + wk] = v;
    }

    // ---- drain cp.async; reuse K/V area for O-partial reduction ----
    CPWAIT0();
    __syncthreads();
    {
        char* preg = attn_smc + A_PART + wid * PART_REG;
        const int r0 = lane >> 2;
#pragma unroll
        for (int nf = 0; nf < 16; nf++) {
            const int col = 8*nf + 2*(lane & 3);
            *reinterpret_cast<float2*>(preg + r0*PART_ROW + col*4) =
                make_float2(O[nf][0], O[nf][1]);
            *reinterpret_cast<float2*>(preg + (r0+8)*PART_ROW + col*4) =
                make_float2(O[nf][2], O[nf][3]);
        }
    }
    __syncthreads();
    {
        const int rr  = tid >> 3;            // 0..31 (q row)
        const int cc  = (tid & 7) * 16;      // col base (floats)
        const int wmh = rr >> 4;
        const int lr  = rr & 15;
        float4 sp = *reinterpret_cast<float4*>(&sums[rr*4]);
        const float inv = 1.f / ((sp.x + sp.y) + (sp.z + sp.w));
        const size_t ob = ((size_t)(b*TT + q0 + rr)) * DD + cc;
#pragma unroll
        for (int s4 = 0; s4 < 4; s4++) {
            float4 a = make_float4(0.f, 0.f, 0.f, 0.f);
#pragma unroll
            for (int k = 0; k < 4; k++) {
                const float4 v = *reinterpret_cast<const float4*>(
                    attn_smc + A_PART + (wmh*4 + k)*PART_REG + lr*PART_ROW + (cc + s4*4)*4);
                a.x += v.x; a.y += v.y; a.z += v.z; a.w += v.w;
            }
            *reinterpret_cast<float4*>(&out[ob + s4*4]) =
                make_float4(a.x*inv, a.y*inv, a.z*inv, a.w*inv);
        }
    }
}

// ---------------------------------------------------------------------------
extern "C" void kernel_launch(void* const* d_in, const int* in_sizes, int n_in,
                              void* d_out, int out_size)
{
    const float* X  = (const float*)d_in[0];
    const float* wQ = (const float*)d_in[1];
    const float* wK = (const float*)d_in[2];
    const float* wV = (const float*)d_in[3];
    float* out = (float*)d_out;

    cudaFuncSetAttribute(proj_mma_kernel, cudaFuncAttributeMaxDynamicSharedMemorySize,
                         PROJ_SMEM_BYTES);
    cudaFuncSetAttribute(attn_mma_kernel, cudaFuncAttributeMaxDynamicSharedMemorySize,
                         ATTN_SMEM);

    rope_table_kernel<<<(TT * (DD/2) + 255) / 256, 256>>>();
    proj_mma_kernel<<<dim3(M_TOT / 64, 3), 256, PROJ_SMEM_BYTES>>>(X, wQ, wK, wV);
    attn_mma_kernel<<<BB * 64, 256, ATTN_SMEM>>>(out);
}